// round 17
// baseline (speedup 1.0000x reference)
#include <cuda_runtime.h>
#include <cuda_fp16.h>
#include <cstdint>

#define T_DIM 256
#define B_DIM 128
#define N_DIM 4
#define L_WIN 64
// one warp = 8 sequences (same t, 8 adjacent b); 4096 single-warp blocks
#define NWARPS 4096

// ---------- fast activations ----------
__device__ __forceinline__ float tanh_a(float x) {
    float y;
    asm("tanh.approx.f32 %0, %1;" : "=f"(y) : "f"(x));
    return y;
}
// sigmoid with the 0.5 input scale FOLDED INTO THE WEIGHTS:
// accumulator already holds 0.5*x, so sigma = 0.5*tanh(acc) + 0.5
__device__ __forceinline__ float sig_pre(float y) {
    return fmaf(0.5f, tanh_a(y), 0.5f);
}
__device__ __forceinline__ uint32_t tanh2u(uint32_t x) {
    uint32_t y;
    asm("tanh.approx.f16x2 %0, %1;" : "=r"(y) : "r"(x));
    return y;
}
// pack two fp32 into f16x2 (lo <- second operand)
__device__ __forceinline__ uint32_t cvt2(float hi, float lo) {
    uint32_t r;
    asm("cvt.rn.f16x2.f32 %0, %1, %2;" : "=r"(r) : "f"(hi), "f"(lo));
    return r;
}

// ---------- fp16 pack / split helpers ----------
__device__ __forceinline__ uint32_t packh2(__half lo, __half hi) {
    __half2 v; v.x = lo; v.y = hi;
    return *reinterpret_cast<uint32_t*>(&v);
}
__device__ __forceinline__ __half2 u2h(uint32_t u) { return *reinterpret_cast<__half2*>(&u); }
__device__ __forceinline__ uint32_t h2u(__half2 h) { return *reinterpret_cast<uint32_t*>(&h); }
__device__ __forceinline__ void splitf(float f, __half& a, __half& b) {
    a = __float2half_rn(f);
    b = __float2half_rn(f - __half2float(a));
}
// fp16 weight pair with fold-in scale (0.5 for sigmoid rows, 1.0 for tanh rows)
__device__ __forceinline__ uint32_t wpack2s(const float* W, int ld, int row, int col, float s) {
    return packh2(__float2half_rn(s * W[row * ld + col]),
                  __float2half_rn(s * W[row * ld + col + 1]));
}

// ---------- tensor core ops ----------
__device__ __forceinline__ void mma16816(float* d, const uint32_t* a,
                                         uint32_t b0, uint32_t b1) {
    asm("mma.sync.aligned.m16n8k16.row.col.f32.f16.f16.f32 "
        "{%0,%1,%2,%3}, {%4,%5,%6,%7}, {%8,%9}, {%0,%1,%2,%3};"
        : "+f"(d[0]), "+f"(d[1]), "+f"(d[2]), "+f"(d[3])
        : "r"(a[0]), "r"(a[1]), "r"(a[2]), "r"(a[3]), "r"(b0), "r"(b1));
}
__device__ __forceinline__ uint32_t movm(uint32_t s) {
    uint32_t d;
    asm("movmatrix.sync.aligned.m8n8.trans.b16 %0, %1;" : "=r"(d) : "r"(s));
    return d;
}

// Gate-grouped ROW PERMUTATION: m-tile 2u = {i[8u..], f[8u..]},
// m-tile 2u+1 = {g[8u..], o[8u..]}; unit-group u uses tiles (2u, 2u+1) only,
// so 8 live fp32 accumulators, activated and released per group.
__device__ __forceinline__ int prow(int mt, int r) {
    int base = (mt & 1) ? ((r & 8) ? 96 : 64) : ((r & 8) ? 32 : 0);
    return base + 8 * (mt >> 1) + (r & 7);
}
// weight fold-scale: sigmoid rows (i,f,o) 0.5; tanh rows (g) 1.0
__device__ __forceinline__ float pscale(int mt, int r) {
    return ((mt & 1) && !(r & 8)) ? 1.0f : 0.5f;   // odd tile, low rows = g-gate
}

__global__ void __launch_bounds__(32, 16) traj_kernel(
    const float* __restrict__ inputs,
    const float* __restrict__ Wih_his, const float* __restrict__ Whh_his,
    const float* __restrict__ bih_his, const float* __restrict__ bhh_his,
    const float* __restrict__ Wih_int, const float* __restrict__ Whh_int,
    const float* __restrict__ bih_int, const float* __restrict__ bhh_int,
    const float* __restrict__ W_out, const float* __restrict__ b_out,
    float* __restrict__ out)
{
    // per-lane Whh A-fragments cached in shared memory (each lane touches only
    // its own 16B slot; loop-invariant addresses -> LDS hoists off the chain).
    __shared__ uint32_t A1s[8][2][32][4];

    const unsigned FULL = 0xffffffffu;
    const int lane = threadIdx.x;
    const int gw = blockIdx.x;
    const int t = (T_DIM - 1) - (gw >> 4);     // long windows first
    const int b0 = (gw & 15) * 8;
    const int g = lane >> 2, tid = lane & 3;
    const __half ONE = __float2half_rn(1.0f);
    const __half2 H05 = __half2half2(__float2half_rn(0.5f));

    // ---- fill his Whh A-frags (fp16, permuted rows, sigmoid-scale folded) ----
#pragma unroll
    for (int mt = 0; mt < 8; mt++) {
#pragma unroll
        for (int kt = 0; kt < 2; kt++) {
            int c0 = 16 * kt + 2 * tid;
            int r0 = prow(mt, g), r1 = prow(mt, g + 8);
            float s0 = pscale(mt, g), s1 = pscale(mt, g + 8);
            A1s[mt][kt][lane][0] = wpack2s(Whh_his, 32, r0, c0, s0);
            A1s[mt][kt][lane][1] = wpack2s(Whh_his, 32, r1, c0, s1);
            A1s[mt][kt][lane][2] = wpack2s(Whh_his, 32, r0, c0 + 8, s0);
            A1s[mt][kt][lane][3] = wpack2s(Whh_his, 32, r1, c0 + 8, s1);
        }
    }
    __syncwarp();

    // ---- his x/bias k-tile A-frags (split-fp16, permuted rows, scaled) ----
    uint32_t XA[8][2];
#pragma unroll
    for (int mt = 0; mt < 8; mt++) {
#pragma unroll
        for (int half = 0; half < 2; half++) {
            int rr = prow(mt, g + 8 * half);
            float s = pscale(mt, g + 8 * half);
            __half wx0_1, wx0_2, wx1_1, wx1_2, bb_1, bb_2;
            splitf(s * Wih_his[rr * 2 + 0], wx0_1, wx0_2);
            splitf(s * Wih_his[rr * 2 + 1], wx1_1, wx1_2);
            splitf(s * (bih_his[rr] + bhh_his[rr]), bb_1, bb_2);
            XA[mt][half] = (tid == 0) ? packh2(wx0_1, wx0_1)
                         : (tid == 1) ? packh2(wx1_1, wx1_1)
                         : (tid == 2) ? packh2(bb_1, wx0_2)
                                      : packh2(wx1_2, bb_2);
        }
    }
    // ---- int A-frags: a0,a1 = W@h (k0-7); a2,a3 = x/bias tile (k8-15) ----
    uint32_t IA1[2][2], IAX[2][2];
#pragma unroll
    for (int mt = 0; mt < 2; mt++) {
#pragma unroll
        for (int half = 0; half < 2; half++) {
            int rr = 16 * mt + g + 8 * half;
            float s = (mt == 1 && half == 0) ? 1.0f : 0.5f;  // g rows unscaled
            IA1[mt][half] = wpack2s(Whh_int, 8, rr, 2 * tid, s);
            __half wx0_1, wx0_2, wx1_1, wx1_2, bb_1, bb_2;
            splitf(s * Wih_int[rr * 2 + 0], wx0_1, wx0_2);
            splitf(s * Wih_int[rr * 2 + 1], wx1_1, wx1_2);
            splitf(s * (bih_int[rr] + bhh_int[rr]), bb_1, bb_2);
            IAX[mt][half] = (tid == 0) ? packh2(wx0_1, wx0_1)
                          : (tid == 1) ? packh2(wx1_1, wx1_1)
                          : (tid == 2) ? packh2(bb_1, wx0_2)
                                       : packh2(wx1_2, bb_2);
        }
    }

    // ---- recurrent state ----
    float cst[4][2];                 // his c: unit-group u, seq-pair slot j
#pragma unroll
    for (int u = 0; u < 4; u++) { cst[u][0] = 0.0f; cst[u][1] = 0.0f; }
    float cint0 = 0.0f, cint1 = 0.0f;
    uint32_t hh[4] = {0, 0, 0, 0};   // his h half2 (unit 8u+g; seqs 2tid,2tid+1)
    uint32_t hintp = 0;              // int h half2
    uint32_t bh1[4] = {0, 0, 0, 0};  // B-frags (k=units)
    uint32_t bih1 = 0;

    int a0 = t - (L_WIN - 1);
    if (a0 < 0) a0 = 0;

    const float2* __restrict__ inp2 = (const float2*)inputs; // [T,B,N] float2
    const long STRIDE = (long)B_DIM * N_DIM;
    long base = ((long)a0 * B_DIM + (b0 + g)) * N_DIM;  // lane loads seq g's x
    float2 xh = inp2[base + 3];   // node -1 (his)
    float2 xi = inp2[base + 0];   // node 0  (int)

    for (int a = a0; a <= t; a++) {
        // prefetch next step
        float2 xhn = xh, xin = xi;
        if (a < t) { xhn = inp2[base + STRIDE + 3]; xin = inp2[base + STRIDE + 0]; }
        base += STRIDE;

        // x B-frags (k rows: x0h,x0l,x1h,x1l,1,x0h,x1h,1)
        __half x0h, x0l, x1h, x1l;
        splitf(xh.x, x0h, x0l); splitf(xh.y, x1h, x1l);
        uint32_t bx = (tid == 0) ? packh2(x0h, x0l)
                    : (tid == 1) ? packh2(x1h, x1l)
                    : (tid == 2) ? packh2(ONE, x0h)
                                 : packh2(x1h, ONE);
        splitf(xi.x, x0h, x0l); splitf(xi.y, x1h, x1l);
        uint32_t bxi = (tid == 0) ? packh2(x0h, x0l)
                     : (tid == 1) ? packh2(x1h, x1l)
                     : (tid == 2) ? packh2(ONE, x0h)
                                  : packh2(x1h, ONE);

        // --- int gates: ONE merged MMA per tile (W@h in k0-7, x/bias in k8-15) ---
        float di[2][4];
#pragma unroll
        for (int mt = 0; mt < 2; mt++) {
            di[mt][0] = di[mt][1] = di[mt][2] = di[mt][3] = 0.0f;
            uint32_t a_[4] = {IA1[mt][0], IA1[mt][1], IAX[mt][0], IAX[mt][1]};
            mma16816(di[mt], a_, bih1, bxi);
        }

        // --- his: per unit-group, 6 MMAs then activate & release ---
        uint32_t nbh[4];
#pragma unroll
        for (int u = 0; u < 4; u++) {
            const int me = 2 * u, mo = 2 * u + 1;
            float de[4] = {0.0f, 0.0f, 0.0f, 0.0f};   // c0,c1 = i; c2,c3 = f (pre-scaled)
            float dg[4] = {0.0f, 0.0f, 0.0f, 0.0f};   // c0,c1 = g; c2,c3 = o (o pre-scaled)
            {
                uint4 v0 = *reinterpret_cast<const uint4*>(A1s[me][0][lane]);
                uint4 v1 = *reinterpret_cast<const uint4*>(A1s[me][1][lane]);
                uint32_t a0_[4] = {v0.x, v0.y, v0.z, v0.w};
                uint32_t a1_[4] = {v1.x, v1.y, v1.z, v1.w};
                mma16816(de, a0_, bh1[0], bh1[1]);
                mma16816(de, a1_, bh1[2], bh1[3]);
                uint32_t xae[4] = {XA[me][0], XA[me][1], 0u, 0u};
                mma16816(de, xae, bx, 0u);
            }
            {
                uint4 v0 = *reinterpret_cast<const uint4*>(A1s[mo][0][lane]);
                uint4 v1 = *reinterpret_cast<const uint4*>(A1s[mo][1][lane]);
                uint32_t a0_[4] = {v0.x, v0.y, v0.z, v0.w};
                uint32_t a1_[4] = {v1.x, v1.y, v1.z, v1.w};
                mma16816(dg, a0_, bh1[0], bh1[1]);
                mma16816(dg, a1_, bh1[2], bh1[3]);
                uint32_t xao[4] = {XA[mo][0], XA[mo][1], 0u, 0u};
                mma16816(dg, xao, bx, 0u);
            }

            // c-path activations fully fp32 (error-sensitive)
            float si0 = sig_pre(de[0]), sf0 = sig_pre(de[2]), tg0 = tanh_a(dg[0]);
            float si1 = sig_pre(de[1]), sf1 = sig_pre(de[3]), tg1 = tanh_a(dg[1]);
            float c0 = fmaf(sf0, cst[u][0], si0 * tg0); cst[u][0] = c0;
            float c1 = fmaf(sf1, cst[u][1], si1 * tg1); cst[u][1] = c1;
            float t0 = tanh_a(c0), t1 = tanh_a(c1);      // fp32 tanh(c)
            // sigma(o) in f16x2 (h is fp16 anyway; bounded extra noise)
            uint32_t po = cvt2(dg[3], dg[2]);            // lo=j0, hi=j1 (pre-scaled)
            __half2 so2 = __hfma2(u2h(tanh2u(po)), H05, H05);
            __half2 tc2 = u2h(cvt2(t1, t0));
            hh[u] = h2u(__hmul2(so2, tc2));              // = packh2(h_j0, h_j1)
            nbh[u] = movm(hh[u]);
        }

        // --- int activations (same split) ---
        {
            float si0 = sig_pre(di[0][0]), sf0 = sig_pre(di[0][2]), tg0 = tanh_a(di[1][0]);
            float si1 = sig_pre(di[0][1]), sf1 = sig_pre(di[0][3]), tg1 = tanh_a(di[1][1]);
            cint0 = fmaf(sf0, cint0, si0 * tg0);
            cint1 = fmaf(sf1, cint1, si1 * tg1);
            float t0 = tanh_a(cint0), t1 = tanh_a(cint1);
            uint32_t po = cvt2(di[1][3], di[1][2]);
            __half2 so2 = __hfma2(u2h(tanh2u(po)), H05, H05);
            __half2 tc2 = u2h(cvt2(t1, t0));
            hintp = h2u(__hmul2(so2, tc2));
            bih1 = movm(hintp);
        }

        bh1[0] = nbh[0]; bh1[1] = nbh[1]; bh1[2] = nbh[2]; bh1[3] = nbh[3];
        xh = xhn; xi = xin;
    }

    // ---- output head (h from half2 pairs) ----
    float p00 = 0.0f, p01 = 0.0f, p10 = 0.0f, p11 = 0.0f;
#pragma unroll
    for (int u = 0; u < 4; u++) {
        int unit = 8 * u + g;
        float2 hf = __half22float2(u2h(hh[u]));   // x: seq 2tid, y: seq 2tid+1
        float wo0 = W_out[unit], wo1 = W_out[40 + unit];
        p00 = fmaf(hf.x, wo0, p00); p01 = fmaf(hf.x, wo1, p01);
        p10 = fmaf(hf.y, wo0, p10); p11 = fmaf(hf.y, wo1, p11);
    }
    {   // int part: lane holds h_int[unit g] for seqs 2tid, 2tid+1
        float2 hf = __half22float2(u2h(hintp));
        float wi0 = W_out[32 + g], wi1 = W_out[72 + g];
        p00 = fmaf(hf.x, wi0, p00); p01 = fmaf(hf.x, wi1, p01);
        p10 = fmaf(hf.y, wi0, p10); p11 = fmaf(hf.y, wi1, p11);
    }
    // reduce across g (lane bits 2-4)
#pragma unroll
    for (int m = 4; m <= 16; m <<= 1) {
        p00 += __shfl_xor_sync(FULL, p00, m);
        p01 += __shfl_xor_sync(FULL, p01, m);
        p10 += __shfl_xor_sync(FULL, p10, m);
        p11 += __shfl_xor_sync(FULL, p11, m);
    }
    if (g == 0) {   // lanes 0-3: tid covers seq pairs (2tid, 2tid+1)
        float4 o;
        o.x = p00 + b_out[0]; o.y = p01 + b_out[1];
        o.z = p10 + b_out[0]; o.w = p11 + b_out[1];
        ((float4*)out)[(t * B_DIM + b0) / 2 + tid] = o;
    }
}

extern "C" void kernel_launch(void* const* d_in, const int* in_sizes, int n_in,
                              void* d_out, int out_size) {
    (void)in_sizes; (void)n_in; (void)out_size;
    const float* inputs  = (const float*)d_in[0];
    const float* Wih_his = (const float*)d_in[1];
    const float* Whh_his = (const float*)d_in[2];
    const float* bih_his = (const float*)d_in[3];
    const float* bhh_his = (const float*)d_in[4];
    const float* Wih_int = (const float*)d_in[5];
    const float* Whh_int = (const float*)d_in[6];
    const float* bih_int = (const float*)d_in[7];
    const float* bhh_int = (const float*)d_in[8];
    const float* W_out   = (const float*)d_in[9];
    const float* b_out   = (const float*)d_in[10];
    float* out = (float*)d_out;

    // 4096 warps (8 seqs each), one warp per 32-thread block;
    // A-fragments in smem keep regs <=128 so 4 warps/SMSP are resident
    traj_kernel<<<NWARPS, 32>>>(inputs, Wih_his, Whh_his, bih_his, bhh_his,
                                Wih_int, Whh_int, bih_int, bhh_int,
                                W_out, b_out, out);
}